// round 16
// baseline (speedup 1.0000x reference)
#include <cuda_runtime.h>
#include <cuda_bf16.h>
#include <cstdint>

typedef uint32_t u32;

#define NVERT 20000
#define NDIRS 8
#define THREADS 256
#define VTILE 32              // vertices per CTA  -> 64 m-rows
#define NTILES 625            // 20000/32 exact
#define NCHUNKS 9             // 8 rings + 1 center chunk, Kc=128 each

// ---- B0 chunk images (d=0 only, 16 f-rows x 128 k), hi/lo bf16, swizzled ----
__device__ __align__(16) __nv_bfloat16 gB0h[NCHUNKS][2048];
__device__ __align__(16) __nv_bfloat16 gB0l[NCHUNKS][2048];

__device__ __host__ __forceinline__ u32 tile_off(int row, int k) {
    return (u32)(row * 256 + (((k >> 3) ^ (row & 7)) << 4) + (k & 7) * 2);
}

__device__ __forceinline__ u32 smem_u32(const void* p) {
    u32 a; asm("{ .reg .u64 t; cvta.to.shared.u64 t, %1; cvt.u32.u64 %0, t; }" : "=r"(a) : "l"(p));
    return a;
}
__device__ __forceinline__ void ldsm4(u32 r[4], u32 addr) {
    asm volatile("ldmatrix.sync.aligned.m8n8.x4.shared.b16 {%0,%1,%2,%3}, [%4];"
                 : "=r"(r[0]), "=r"(r[1]), "=r"(r[2]), "=r"(r[3]) : "r"(addr));
}
__device__ __forceinline__ void mma16816(float c[4], const u32 a[4], u32 b0, u32 b1) {
    asm volatile(
        "mma.sync.aligned.m16n8k16.row.col.f32.bf16.bf16.f32 "
        "{%0,%1,%2,%3}, {%4,%5,%6,%7}, {%8,%9}, {%0,%1,%2,%3};"
        : "+f"(c[0]), "+f"(c[1]), "+f"(c[2]), "+f"(c[3])
        : "r"(a[0]), "r"(a[1]), "r"(a[2]), "r"(a[3]), "r"(b0), "r"(b1));
}
__device__ __forceinline__ void cp16(u32 dst, const void* src) {
    asm volatile("cp.async.cg.shared.global [%0], [%1], 16;" :: "r"(dst), "l"(src) : "memory");
}

// ---- prep kernel: build d=0 B images: B0[f][dp*16+c] = kernel[kc][dp][c][f] ----
__global__ void prep_B0(const float* __restrict__ kern, const float* __restrict__ ck) {
    int id = blockIdx.x * blockDim.x + threadIdx.x;     // 18432
    if (id >= NCHUNKS * 16 * 128) return;
    int k  = id & 127;
    int f  = (id >> 7) & 15;
    int kc = id >> 11;
    int dp = k >> 4, c = k & 15;
    float val;
    if (kc < 8) val = kern[((kc * 8 + dp) * 16 + c) * 16 + f];
    else        val = (dp == 0) ? ck[c * 16 + f] : 0.f;
    __nv_bfloat16 hi = __float2bfloat16(val);
    __nv_bfloat16 lo = __float2bfloat16(val - __bfloat162float(hi));
    u32 e = tile_off(f, k) >> 1;
    gB0h[kc][e] = hi;
    gB0l[kc][e] = lo;
}

// ---- smem layout ----
// A hi 16K + A lo 16K @0 ; B hi 4K @32K ; B lo 4K @36K ;
// idx stage double-buffered @40K: per buf {cont 3K, ang 3K, wb 3K} = 9K
#define A_LO_OFF 16384
#define SB_BASE  32768
#define B_LO_OFF 4096
#define SIDX     40960
#define IDX_BUF  9216
#define SMEM_TOTAL (40960 + 2*IDX_BUF)     // 59392

// convert 4 floats (k-quad q of row m) to hi/lo bf16 and store 8B each image
__device__ __forceinline__ void store_quad(char* sm, int m, int dp, int q, float4 z) {
    __nv_bfloat162 h0 = __floats2bfloat162_rn(z.x, z.y);
    __nv_bfloat162 h1 = __floats2bfloat162_rn(z.z, z.w);
    __nv_bfloat162 l0 = __floats2bfloat162_rn(z.x - __low2float(h0), z.y - __high2float(h0));
    __nv_bfloat162 l1 = __floats2bfloat162_rn(z.z - __low2float(h1), z.w - __high2float(h1));
    u32 off = (u32)(m * 256 + ((((dp << 1) | (q >> 1)) ^ (m & 7)) << 4) + (q & 1) * 8);
    uint2 H; H.x = *reinterpret_cast<u32*>(&h0); H.y = *reinterpret_cast<u32*>(&h1);
    uint2 L; L.x = *reinterpret_cast<u32*>(&l0); L.y = *reinterpret_cast<u32*>(&l1);
    *reinterpret_cast<uint2*>(sm + off) = H;
    *reinterpret_cast<uint2*>(sm + off + A_LO_OFF) = L;
}

__global__ __launch_bounds__(THREADS, 3)
void geodesic_occ3_kernel(const float* __restrict__ y,
                          const int*   __restrict__ contributors,
                          const float* __restrict__ weights_bary,
                          const int*   __restrict__ angles,
                          const float* __restrict__ bias,
                          float*       __restrict__ out)
{
    extern __shared__ char sm[];
    const u32 smb = smem_u32(sm);
    const int tid = threadIdx.x;
    const int wid = tid >> 5;
    const int lid = tid & 31;
    const int v0  = blockIdx.x * VTILE;         // 32 vertices => 64 rows (m = vl*2 + b)
    const int m0  = (wid >> 1) * 16;            // warp's 16-row m-strip
    const int nh  = wid & 1;                    // warp's d-half: d in [nh*4, nh*4+4)

    float acc[32];
    #pragma unroll
    for (int i = 0; i < 32; ++i) acc[i] = 0.f;

    const int lrow  = (lid & 7) + ((lid >> 3) & 1) * 8;   // 0..15
    const int khalf = (lid >> 4);

    const int mA = m0 + lrow;
    const u32 a_row = (u32)(mA * 256);
    const u32 a_xor = (u32)((mA & 7) << 4);
    const u32 b_row = (u32)(lrow * 256);
    const u32 b_xor = (u32)((lrow & 7) << 4);
    const u32 a_base = smb + a_row;
    const u32 sb = smb + SB_BASE + b_row;

    // quad-cooperative gather geometry
    const int q  = lid & 3;
    const int qt = tid >> 2;

    const float4* y4 = (const float4*)y;

    // ---- index-stage copy helper (192 cp16 per array, 3 arrays) ----
    // global: array[(v*8+kcn)*24 .. +24) ints per v; 96B rows at 768B stride
    auto copy_idx = [&](int kcn, int buf) {
        const char* srcs[3] = { (const char*)contributors,
                                (const char*)angles,
                                (const char*)weights_bary };
        u32 dbase = smb + SIDX + (u32)buf * IDX_BUF;
        #pragma unroll 1
        for (int i = tid; i < 576; i += THREADS) {
            int arr = i / 192;
            int r   = i % 192;
            int vl  = r / 6;
            int s   = r % 6;
            const char* src = srcs[arr] + (size_t)(((v0 + vl) * 8 + kcn) * 96) + s * 16;
            cp16(dbase + (u32)arr * 3072 + (u32)(vl * 96 + s * 16), src);
        }
    };

    // ---- prologue: stage chunk 0 indices ----
    copy_idx(0, 0);
    asm volatile("cp.async.commit_group;\n\tcp.async.wait_group 0;" ::: "memory");
    __syncthreads();

    #pragma unroll 1
    for (int kc = 0; kc < NCHUNKS; ++kc) {
        if (kc > 0) __syncthreads();            // prev MMA done; idx buf safe to reuse

        // ---- issue async copies: B[kc] (8KB) + next chunk's indices (9KB) ----
        {
            u32 off = (u32)tid * 16;
            cp16(smb + SB_BASE + off, (const char*)(&gB0h[kc][0]) + off);
            cp16(smb + SB_BASE + B_LO_OFF + off, (const char*)(&gB0l[kc][0]) + off);
            if (kc + 1 < 8) copy_idx(kc + 1, (kc + 1) & 1);
            asm volatile("cp.async.commit_group;" ::: "memory");
        }

        // ---- gather: one (v,dp) task per QUAD; indices from smem (LDS) ----
        const int* scont = (const int*)  (sm + SIDX + (size_t)(kc & 1) * IDX_BUF);
        const int* sang  = (const int*)  (sm + SIDX + (size_t)(kc & 1) * IDX_BUF + 3072);
        const float* swb = (const float*)(sm + SIDX + (size_t)(kc & 1) * IDX_BUF + 6144);
        #pragma unroll 1
        for (int rr = 0; rr < 4; ++rr) {
            int t  = qt + rr * 64;
            int dp = t & 7;
            int vl = t >> 3;
            float4 z0, z1;
            if (kc < 8) {
                int sbi = vl * 24 + dp * 3;
                int   i0 = scont[sbi+0] * 8 + sang[sbi+0];
                int   i1 = scont[sbi+1] * 8 + sang[sbi+1];
                int   i2 = scont[sbi+2] * 8 + sang[sbi+2];
                float w0 = swb[sbi+0];
                float w1 = swb[sbi+1];
                float w2 = swb[sbi+2];
                float4 a0 = __ldg(y4 + (u32)i0 * 4 + q);
                float4 a1 = __ldg(y4 + (u32)i1 * 4 + q);
                float4 a2 = __ldg(y4 + (u32)i2 * 4 + q);
                float4 c0 = __ldg(y4 + (u32)i0 * 4 + q + NVERT * NDIRS * 4);
                float4 c1 = __ldg(y4 + (u32)i1 * 4 + q + NVERT * NDIRS * 4);
                float4 c2 = __ldg(y4 + (u32)i2 * 4 + q + NVERT * NDIRS * 4);
                z0.x = w0*a0.x + w1*a1.x + w2*a2.x;
                z0.y = w0*a0.y + w1*a1.y + w2*a2.y;
                z0.z = w0*a0.z + w1*a1.z + w2*a2.z;
                z0.w = w0*a0.w + w1*a1.w + w2*a2.w;
                z1.x = w0*c0.x + w1*c1.x + w2*c2.x;
                z1.y = w0*c0.y + w1*c1.y + w2*c2.y;
                z1.z = w0*c0.z + w1*c1.z + w2*c2.z;
                z1.w = w0*c0.w + w1*c1.w + w2*c2.w;
            } else {
                int idx = (v0 + vl) * 8 + dp;
                z0 = __ldg(y4 + (u32)idx * 4 + q);
                z1 = __ldg(y4 + (u32)idx * 4 + q + NVERT * NDIRS * 4);
            }
            store_quad(sm, vl*2 + 0, dp, q, z0);
            store_quad(sm, vl*2 + 1, dp, q, z1);
        }

        asm volatile("cp.async.wait_group 0;" ::: "memory");
        __syncthreads();

        // ---- HMMA with circulant rotation: B fragment at j = (ks - d) & 7 ----
        #pragma unroll 1
        for (int ks = 0; ks < 8; ++ks) {
            u32 cc4 = (u32)((ks*2 + khalf) << 4);
            u32 aaddr = a_base + (cc4 ^ a_xor);
            u32 afh[4], afl[4];
            ldsm4(afh, aaddr);
            ldsm4(afl, aaddr + A_LO_OFF);
            #pragma unroll
            for (int p = 0; p < 4; ++p) {
                int d = nh*4 + p;
                int j = (ks - d) & 7;
                u32 ccB = (u32)((j*2 + khalf) << 4);
                u32 baddr = sb + (ccB ^ b_xor);
                u32 bfh[4], bfl[4];
                ldsm4(bfh, baddr);
                ldsm4(bfl, baddr + B_LO_OFF);
                mma16816(&acc[(p*2+0)*4], afh, bfh[0], bfh[2]);
                mma16816(&acc[(p*2+1)*4], afh, bfh[1], bfh[3]);
                mma16816(&acc[(p*2+0)*4], afh, bfl[0], bfl[2]);
                mma16816(&acc[(p*2+1)*4], afh, bfl[1], bfl[3]);
                mma16816(&acc[(p*2+0)*4], afl, bfh[0], bfh[2]);
                mma16816(&acc[(p*2+1)*4], afl, bfh[1], bfh[3]);
            }
        }
    }

    // ---- epilogue: in-thread max over this warp's 4 d values, then combine ----
    __syncthreads();
    float* scratch = (float*)sm;                // [nh][row 0..63][f 0..15]
    const int fa = (lid & 3) * 2;
    const int r0 = m0 + (lid >> 2);
    #pragma unroll
    for (int half = 0; half < 2; ++half)
        #pragma unroll
        for (int rs = 0; rs < 2; ++rs)
            #pragma unroll
            for (int j = 0; j < 2; ++j) {
                float v = acc[(0*2+half)*4 + rs*2 + j];
                v = fmaxf(v, acc[(1*2+half)*4 + rs*2 + j]);
                v = fmaxf(v, acc[(2*2+half)*4 + rs*2 + j]);
                v = fmaxf(v, acc[(3*2+half)*4 + rs*2 + j]);
                scratch[nh*1024 + (r0 + rs*8)*16 + half*8 + fa + j] = v;
            }
    __syncthreads();

    {
        int row = tid >> 2;
        int f4  = (tid & 3) * 4;
        float4 A = *(float4*)&scratch[row*16 + f4];
        float4 Bv = *(float4*)&scratch[1024 + row*16 + f4];
        float4 bb = *(const float4*)&bias[f4];
        float4 r;
        r.x = fmaxf(fmaxf(A.x, Bv.x) + bb.x, 0.f);
        r.y = fmaxf(fmaxf(A.y, Bv.y) + bb.y, 0.f);
        r.z = fmaxf(fmaxf(A.z, Bv.z) + bb.z, 0.f);
        r.w = fmaxf(fmaxf(A.w, Bv.w) + bb.w, 0.f);
        int b = row & 1, v = v0 + (row >> 1);
        *(float4*)&out[((u32)b * NVERT + v) * 16 + f4] = r;
    }
}

extern "C" void kernel_launch(void* const* d_in, const int* in_sizes, int n_in,
                              void* d_out, int out_size)
{
    (void)in_sizes; (void)n_in; (void)out_size;
    const float* y            = (const float*)d_in[0];
    const int*   contributors = (const int*)  d_in[1];
    const float* weights_bary = (const float*)d_in[2];
    const int*   angles       = (const int*)  d_in[3];
    const float* kern         = (const float*)d_in[4];
    const float* center_k     = (const float*)d_in[5];
    const float* bias         = (const float*)d_in[6];
    float* out = (float*)d_out;

    prep_B0<<<(NCHUNKS*16*128 + 255)/256, 256>>>(kern, center_k);

    cudaFuncSetAttribute(geodesic_occ3_kernel,
                         cudaFuncAttributeMaxDynamicSharedMemorySize, SMEM_TOTAL);
    geodesic_occ3_kernel<<<NTILES, THREADS, SMEM_TOTAL>>>(
        y, contributors, weights_bary, angles, bias, out);
}

// round 17
// speedup vs baseline: 1.0936x; 1.0936x over previous
#include <cuda_runtime.h>
#include <cuda_bf16.h>
#include <cstdint>

typedef uint32_t u32;

#define NVERT 20000
#define NDIRS 8
#define THREADS 256
#define VTILE 32              // vertices per CTA  -> 64 m-rows
#define NTILES 625            // 20000/32 exact
#define NCHUNKS 9             // 8 rings + 1 center chunk, Kc=128 each

// ---- B0 chunk images (d=0 only, 16 f-rows x 128 k), hi/lo bf16, swizzled ----
__device__ __align__(16) __nv_bfloat16 gB0h[NCHUNKS][2048];
__device__ __align__(16) __nv_bfloat16 gB0l[NCHUNKS][2048];

__device__ __host__ __forceinline__ u32 tile_off(int row, int k) {
    return (u32)(row * 256 + (((k >> 3) ^ (row & 7)) << 4) + (k & 7) * 2);
}

__device__ __forceinline__ u32 smem_u32(const void* p) {
    u32 a; asm("{ .reg .u64 t; cvta.to.shared.u64 t, %1; cvt.u32.u64 %0, t; }" : "=r"(a) : "l"(p));
    return a;
}
__device__ __forceinline__ void ldsm4(u32 r[4], u32 addr) {
    asm volatile("ldmatrix.sync.aligned.m8n8.x4.shared.b16 {%0,%1,%2,%3}, [%4];"
                 : "=r"(r[0]), "=r"(r[1]), "=r"(r[2]), "=r"(r[3]) : "r"(addr));
}
__device__ __forceinline__ void mma16816(float c[4], const u32 a[4], u32 b0, u32 b1) {
    asm volatile(
        "mma.sync.aligned.m16n8k16.row.col.f32.bf16.bf16.f32 "
        "{%0,%1,%2,%3}, {%4,%5,%6,%7}, {%8,%9}, {%0,%1,%2,%3};"
        : "+f"(c[0]), "+f"(c[1]), "+f"(c[2]), "+f"(c[3])
        : "r"(a[0]), "r"(a[1]), "r"(a[2]), "r"(a[3]), "r"(b0), "r"(b1));
}
__device__ __forceinline__ void cp16(u32 dst, const void* src) {
    asm volatile("cp.async.cg.shared.global [%0], [%1], 16;" :: "r"(dst), "l"(src) : "memory");
}

// ---- prep kernel: build d=0 B images: B0[f][dp*16+c] = kernel[kc][dp][c][f] ----
__global__ void prep_B0(const float* __restrict__ kern, const float* __restrict__ ck) {
    int id = blockIdx.x * blockDim.x + threadIdx.x;     // 18432
    if (id >= NCHUNKS * 16 * 128) return;
    int k  = id & 127;
    int f  = (id >> 7) & 15;
    int kc = id >> 11;
    int dp = k >> 4, c = k & 15;
    float val;
    if (kc < 8) val = kern[((kc * 8 + dp) * 16 + c) * 16 + f];
    else        val = (dp == 0) ? ck[c * 16 + f] : 0.f;
    __nv_bfloat16 hi = __float2bfloat16(val);
    __nv_bfloat16 lo = __float2bfloat16(val - __bfloat162float(hi));
    u32 e = tile_off(f, k) >> 1;
    gB0h[kc][e] = hi;
    gB0l[kc][e] = lo;
}

// ---- smem: A hi 16K + A lo 16K @0 ; B hi 4K @32K ; B lo 4K @36K = 40KB ----
#define A_LO_OFF 16384
#define SB_BASE  32768
#define B_LO_OFF 4096
#define SMEM_TOTAL 40960

// convert 4 floats (k-quad q of row m) to hi/lo bf16 and store 8B each image
__device__ __forceinline__ void store_quad(char* sm, int m, int dp, int q, float4 z) {
    __nv_bfloat162 h0 = __floats2bfloat162_rn(z.x, z.y);
    __nv_bfloat162 h1 = __floats2bfloat162_rn(z.z, z.w);
    __nv_bfloat162 l0 = __floats2bfloat162_rn(z.x - __low2float(h0), z.y - __high2float(h0));
    __nv_bfloat162 l1 = __floats2bfloat162_rn(z.z - __low2float(h1), z.w - __high2float(h1));
    u32 off = (u32)(m * 256 + ((((dp << 1) | (q >> 1)) ^ (m & 7)) << 4) + (q & 1) * 8);
    uint2 H; H.x = *reinterpret_cast<u32*>(&h0); H.y = *reinterpret_cast<u32*>(&h1);
    uint2 L; L.x = *reinterpret_cast<u32*>(&l0); L.y = *reinterpret_cast<u32*>(&l1);
    *reinterpret_cast<uint2*>(sm + off) = H;
    *reinterpret_cast<uint2*>(sm + off + A_LO_OFF) = L;
}

__global__ __launch_bounds__(THREADS, 3)
void geodesic_dpair_kernel(const float* __restrict__ y,
                           const int*   __restrict__ contributors,
                           const float* __restrict__ weights_bary,
                           const int*   __restrict__ angles,
                           const float* __restrict__ bias,
                           float*       __restrict__ out)
{
    extern __shared__ char sm[];
    const u32 smb = smem_u32(sm);
    const int tid = threadIdx.x;
    const int wid = tid >> 5;
    const int lid = tid & 31;
    const int v0  = blockIdx.x * VTILE;         // 32 vertices => 64 rows (m = vl*2 + b)
    const int ms  = wid & 1;                    // m-half: rows [ms*32, ms*32+32)
    const int dg  = wid >> 1;                   // d-group: d in {dg*2, dg*2+1}
    const int d0  = dg * 2;

    // accumulators: [mt 0..1][nt = dlocal*2 + fhalf][4]
    float acc[32];
    #pragma unroll
    for (int i = 0; i < 32; ++i) acc[i] = 0.f;

    const int lrow  = (lid & 7) + ((lid >> 3) & 1) * 8;   // 0..15
    const int khalf = (lid >> 4);

    const int mA0 = ms * 32 + lrow;             // mt0 row; mt1 = +16
    const u32 a_xor  = (u32)((mA0 & 7) << 4);
    const u32 a_b0   = smb + (u32)(mA0 * 256);  // mt0 base
    const u32 b_row  = (u32)(lrow * 256);       // B row = f = lrow
    const u32 b_xor  = (u32)((lrow & 7) << 4);
    const u32 sb     = smb + SB_BASE + b_row;

    // quad-cooperative gather geometry
    const int q     = lid & 3;
    const int qt    = tid >> 2;
    const int lbase = lid & ~3;

    const float4* y4 = (const float4*)y;

    #pragma unroll 1
    for (int kc = 0; kc < NCHUNKS; ++kc) {
        if (kc > 0) __syncthreads();            // prev MMA done reading A and B

        // ---- copy this chunk's 8KB B image ----
        {
            u32 off = (u32)tid * 16;
            cp16(smb + SB_BASE + off, (const char*)(&gB0h[kc][0]) + off);
            cp16(smb + SB_BASE + B_LO_OFF + off, (const char*)(&gB0l[kc][0]) + off);
            asm volatile("cp.async.commit_group;" ::: "memory");
        }

        // ---- gather: one (v,dp) task per QUAD; lane q owns 16B c-quad ----
        #pragma unroll 1
        for (int rr = 0; rr < 4; ++rr) {
            int t  = qt + rr * 64;
            int dp = t & 7;
            int vl = t >> 3;
            int v  = v0 + vl;
            float4 z0, z1;
            if (kc < 8) {
                int ibase = ((v * 8 + kc) * 8 + dp) * 3;
                int   idxv = 0;
                float wv   = 0.f;
                if (q < 3) {
                    idxv = __ldg(&contributors[ibase + q]) * 8 + __ldg(&angles[ibase + q]);
                    wv   = __ldg(&weights_bary[ibase + q]);
                }
                int   i0 = __shfl_sync(0xffffffffu, idxv, lbase + 0);
                int   i1 = __shfl_sync(0xffffffffu, idxv, lbase + 1);
                int   i2 = __shfl_sync(0xffffffffu, idxv, lbase + 2);
                float w0 = __shfl_sync(0xffffffffu, wv,   lbase + 0);
                float w1 = __shfl_sync(0xffffffffu, wv,   lbase + 1);
                float w2 = __shfl_sync(0xffffffffu, wv,   lbase + 2);
                float4 a0 = __ldg(y4 + (u32)i0 * 4 + q);
                float4 a1 = __ldg(y4 + (u32)i1 * 4 + q);
                float4 a2 = __ldg(y4 + (u32)i2 * 4 + q);
                float4 c0 = __ldg(y4 + (u32)i0 * 4 + q + NVERT * NDIRS * 4);
                float4 c1 = __ldg(y4 + (u32)i1 * 4 + q + NVERT * NDIRS * 4);
                float4 c2 = __ldg(y4 + (u32)i2 * 4 + q + NVERT * NDIRS * 4);
                z0.x = w0*a0.x + w1*a1.x + w2*a2.x;
                z0.y = w0*a0.y + w1*a1.y + w2*a2.y;
                z0.z = w0*a0.z + w1*a1.z + w2*a2.z;
                z0.w = w0*a0.w + w1*a1.w + w2*a2.w;
                z1.x = w0*c0.x + w1*c1.x + w2*c2.x;
                z1.y = w0*c0.y + w1*c1.y + w2*c2.y;
                z1.z = w0*c0.z + w1*c1.z + w2*c2.z;
                z1.w = w0*c0.w + w1*c1.w + w2*c2.w;
            } else {
                int idx = (v0 + vl) * 8 + dp;
                z0 = __ldg(y4 + (u32)idx * 4 + q);
                z1 = __ldg(y4 + (u32)idx * 4 + q + NVERT * NDIRS * 4);
            }
            store_quad(sm, vl*2 + 0, dp, q, z0);
            store_quad(sm, vl*2 + 1, dp, q, z1);
        }

        asm volatile("cp.async.wait_group 0;" ::: "memory");
        __syncthreads();

        if (kc < 8) {
            // ---- MMA: d-pair mapping with rolling B reuse ----
            // prev = B(j for d0+1 at ks=0) = B((-d0-1)&7)
            u32 ph[4], pl[4];
            {
                int jp = (-(d0 + 1)) & 7;
                u32 ccB = (u32)((jp*2 + khalf) << 4);
                u32 baddr = sb + (ccB ^ b_xor);
                ldsm4(ph, baddr);
                ldsm4(pl, baddr + B_LO_OFF);
            }
            #pragma unroll 1
            for (int ks = 0; ks < 8; ++ks) {
                u32 cc4 = (u32)((ks*2 + khalf) << 4);
                u32 afh0[4], afl0[4], afh1[4], afl1[4];
                u32 aaddr0 = a_b0 + (cc4 ^ a_xor);
                ldsm4(afh0, aaddr0);
                ldsm4(afl0, aaddr0 + A_LO_OFF);
                ldsm4(afh1, aaddr0 + 4096);
                ldsm4(afl1, aaddr0 + 4096 + A_LO_OFF);
                // new B for d0: j0 = (ks - d0) & 7
                u32 bh[4], bl[4];
                {
                    int j0 = (ks - d0) & 7;
                    u32 ccB = (u32)((j0*2 + khalf) << 4);
                    u32 baddr = sb + (ccB ^ b_xor);
                    ldsm4(bh, baddr);
                    ldsm4(bl, baddr + B_LO_OFF);
                }
                // d0 (dlocal 0): nt 0,1
                mma16816(&acc[(0*4+0)*4], afh0, bh[0], bh[2]);
                mma16816(&acc[(0*4+1)*4], afh0, bh[1], bh[3]);
                mma16816(&acc[(1*4+0)*4], afh1, bh[0], bh[2]);
                mma16816(&acc[(1*4+1)*4], afh1, bh[1], bh[3]);
                mma16816(&acc[(0*4+0)*4], afh0, bl[0], bl[2]);
                mma16816(&acc[(0*4+1)*4], afh0, bl[1], bl[3]);
                mma16816(&acc[(1*4+0)*4], afh1, bl[0], bl[2]);
                mma16816(&acc[(1*4+1)*4], afh1, bl[1], bl[3]);
                mma16816(&acc[(0*4+0)*4], afl0, bh[0], bh[2]);
                mma16816(&acc[(0*4+1)*4], afl0, bh[1], bh[3]);
                mma16816(&acc[(1*4+0)*4], afl1, bh[0], bh[2]);
                mma16816(&acc[(1*4+1)*4], afl1, bh[1], bh[3]);
                // d1 (dlocal 1): nt 2,3 — uses prev B
                mma16816(&acc[(0*4+2)*4], afh0, ph[0], ph[2]);
                mma16816(&acc[(0*4+3)*4], afh0, ph[1], ph[3]);
                mma16816(&acc[(1*4+2)*4], afh1, ph[0], ph[2]);
                mma16816(&acc[(1*4+3)*4], afh1, ph[1], ph[3]);
                mma16816(&acc[(0*4+2)*4], afh0, pl[0], pl[2]);
                mma16816(&acc[(0*4+3)*4], afh0, pl[1], pl[3]);
                mma16816(&acc[(1*4+2)*4], afh1, pl[0], pl[2]);
                mma16816(&acc[(1*4+3)*4], afh1, pl[1], pl[3]);
                mma16816(&acc[(0*4+2)*4], afl0, ph[0], ph[2]);
                mma16816(&acc[(0*4+3)*4], afl0, ph[1], ph[3]);
                mma16816(&acc[(1*4+2)*4], afl1, ph[0], ph[2]);
                mma16816(&acc[(1*4+3)*4], afl1, ph[1], ph[3]);
                // roll
                #pragma unroll
                for (int i = 0; i < 4; ++i) { ph[i] = bh[i]; pl[i] = bl[i]; }
            }
        } else {
            // ---- center chunk fast path: only j=0 is nonzero ----
            u32 bh[4], bl[4];
            {
                u32 ccB = (u32)(khalf << 4);      // j=0
                u32 baddr = sb + (ccB ^ b_xor);
                ldsm4(bh, baddr);
                ldsm4(bl, baddr + B_LO_OFF);
            }
            #pragma unroll
            for (int dl = 0; dl < 2; ++dl) {
                int ks = d0 + dl;                 // j=(ks-d)&7==0 only at ks=d
                u32 cc4 = (u32)((ks*2 + khalf) << 4);
                u32 afh0[4], afl0[4], afh1[4], afl1[4];
                u32 aaddr0 = a_b0 + (cc4 ^ a_xor);
                ldsm4(afh0, aaddr0);
                ldsm4(afl0, aaddr0 + A_LO_OFF);
                ldsm4(afh1, aaddr0 + 4096);
                ldsm4(afl1, aaddr0 + 4096 + A_LO_OFF);
                int nt0 = dl*2, nt1 = dl*2 + 1;
                mma16816(&acc[(0*4+nt0)*4], afh0, bh[0], bh[2]);
                mma16816(&acc[(0*4+nt1)*4], afh0, bh[1], bh[3]);
                mma16816(&acc[(1*4+nt0)*4], afh1, bh[0], bh[2]);
                mma16816(&acc[(1*4+nt1)*4], afh1, bh[1], bh[3]);
                mma16816(&acc[(0*4+nt0)*4], afh0, bl[0], bl[2]);
                mma16816(&acc[(0*4+nt1)*4], afh0, bl[1], bl[3]);
                mma16816(&acc[(1*4+nt0)*4], afh1, bl[0], bl[2]);
                mma16816(&acc[(1*4+nt1)*4], afh1, bl[1], bl[3]);
                mma16816(&acc[(0*4+nt0)*4], afl0, bh[0], bh[2]);
                mma16816(&acc[(0*4+nt1)*4], afl0, bh[1], bh[3]);
                mma16816(&acc[(1*4+nt0)*4], afl1, bh[0], bh[2]);
                mma16816(&acc[(1*4+nt1)*4], afl1, bh[1], bh[3]);
            }
        }
    }

    // ---- epilogue: max over warp's 2 d in-thread, 4-way dgroup reduce ----
    __syncthreads();                            // everyone done with A smem
    float* scratch = (float*)sm;                // [dg 0..3][row 0..63][f 0..15]
    const int fa = (lid & 3) * 2;
    const int rbase = ms * 32 + (lid >> 2);
    #pragma unroll
    for (int mt = 0; mt < 2; ++mt)
        #pragma unroll
        for (int fh = 0; fh < 2; ++fh)
            #pragma unroll
            for (int rs = 0; rs < 2; ++rs)
                #pragma unroll
                for (int jj = 0; jj < 2; ++jj) {
                    float v = fmaxf(acc[(mt*4 + 0*2 + fh)*4 + rs*2 + jj],
                                    acc[(mt*4 + 1*2 + fh)*4 + rs*2 + jj]);
                    int row = rbase + mt*16 + rs*8;
                    int f   = fh*8 + fa + jj;
                    scratch[dg*1024 + row*16 + f] = v;
                }
    __syncthreads();

    // final combine across 4 dgroups + bias + relu + store (float4 per thread)
    {
        int row = tid >> 2;
        int f4  = (tid & 3) * 4;
        float4 A  = *(float4*)&scratch[         row*16 + f4];
        float4 Bv = *(float4*)&scratch[1024 +   row*16 + f4];
        float4 C  = *(float4*)&scratch[2048 +   row*16 + f4];
        float4 D  = *(float4*)&scratch[3072 +   row*16 + f4];
        float4 bb = *(const float4*)&bias[f4];
        float4 r;
        r.x = fmaxf(fmaxf(fmaxf(A.x, Bv.x), fmaxf(C.x, D.x)) + bb.x, 0.f);
        r.y = fmaxf(fmaxf(fmaxf(A.y, Bv.y), fmaxf(C.y, D.y)) + bb.y, 0.f);
        r.z = fmaxf(fmaxf(fmaxf(A.z, Bv.z), fmaxf(C.z, D.z)) + bb.z, 0.f);
        r.w = fmaxf(fmaxf(fmaxf(A.w, Bv.w), fmaxf(C.w, D.w)) + bb.w, 0.f);
        int b = row & 1, v = v0 + (row >> 1);
        *(float4*)&out[((u32)b * NVERT + v) * 16 + f4] = r;
    }
}

extern "C" void kernel_launch(void* const* d_in, const int* in_sizes, int n_in,
                              void* d_out, int out_size)
{
    (void)in_sizes; (void)n_in; (void)out_size;
    const float* y            = (const float*)d_in[0];
    const int*   contributors = (const int*)  d_in[1];
    const float* weights_bary = (const float*)d_in[2];
    const int*   angles       = (const int*)  d_in[3];
    const float* kern         = (const float*)d_in[4];
    const float* center_k     = (const float*)d_in[5];
    const float* bias         = (const float*)d_in[6];
    float* out = (float*)d_out;

    prep_B0<<<(NCHUNKS*16*128 + 255)/256, 256>>>(kern, center_k);

    cudaFuncSetAttribute(geodesic_dpair_kernel,
                         cudaFuncAttributeMaxDynamicSharedMemorySize, SMEM_TOTAL);
    geodesic_dpair_kernel<<<NTILES, THREADS, SMEM_TOTAL>>>(
        y, contributors, weights_bary, angles, bias, out);
}